// round 1
// baseline (speedup 1.0000x reference)
#include <cuda_runtime.h>
#include <cuda_bf16.h>
#include <cstdint>

// ---------------------------------------------------------------------------
// ThunderHubLM: embed -> 4x thunder_core -> layernorm -> {logits, recon, states}
// B=2, L=2048 (M=4096 rows), D=256, S=8, DEPTH=4, VOCAB=32000
// All fp32. Round 1: correct baseline, FFMA-tiled SGEMM for all matmuls.
// ---------------------------------------------------------------------------

#define D_     256
#define S_     8
#define DS_    264   // D + S
#define DEPTH_ 4
#define VOCAB_ 32000
#define MROWS  4096  // B * L
#define L_     2048
#define B_     2

// Scratch (device globals; no allocation allowed)
__device__ float g_h[MROWS * D_];        // hidden state between layers
__device__ float g_comb[MROWS * DS_];    // combined = h@Wi + bi; cols 256..263 overwritten by scan states
__device__ float g_gate[MROWS * S_];     // sigmoid gates
__device__ float g_hn[MROWS * D_];       // layernormed h

// ---------------------------------------------------------------------------
// Embedding gather: h[row] = embed_table[x_t[row]]
// ---------------------------------------------------------------------------
__global__ void embed_kernel(const int* __restrict__ x, const float* __restrict__ tab)
{
    int row = blockIdx.x;
    int t   = threadIdx.x;  // 64 threads, each one float4
    int tok = x[row];
    const float4* src = reinterpret_cast<const float4*>(tab + (size_t)tok * D_);
    float4* dst = reinterpret_cast<float4*>(g_h + (size_t)row * D_);
    dst[t] = src[t];
}

// ---------------------------------------------------------------------------
// Generic tiled SGEMM with bias: C[M,N] = A[M,K] @ B[K,N] + bias[N]
// Row-major, lda=K, ldb=N, ldc=N. 128x128 tile, TK=8, 256 threads, 8x8 micro.
// Requires K % 8 == 0 and 4-float alignment of K and N strides (holds here).
// ---------------------------------------------------------------------------
__global__ void __launch_bounds__(256)
sgemm_bias(const float* __restrict__ A, const float* __restrict__ B,
           const float* __restrict__ bias, float* __restrict__ C,
           int M, int N, int K)
{
    __shared__ float As[8][128];
    __shared__ float Bs[8][128];

    int tid = threadIdx.x;
    int tx = tid & 15;          // 0..15 -> N direction
    int ty = tid >> 4;          // 0..15 -> M direction
    int bm = blockIdx.y * 128;
    int bn = blockIdx.x * 128;

    float acc[8][8];
#pragma unroll
    for (int i = 0; i < 8; i++)
#pragma unroll
        for (int j = 0; j < 8; j++) acc[i][j] = 0.f;

    // A staging: thread t loads row bm + t/2, k cols k0 + (t&1)*4 .. +3  (float4)
    int a_row  = tid >> 1;
    int a_kc   = (tid & 1) * 4;
    // B staging: thread t loads row k0 + t/32, cols bn + (t&31)*4 .. +3 (float4)
    int b_kk   = tid >> 5;
    int b_col  = (tid & 31) * 4;

    for (int k0 = 0; k0 < K; k0 += 8) {
        // ---- load A tile ----
        {
            int gr = bm + a_row;
            int gk = k0 + a_kc;
            float4 v = make_float4(0.f, 0.f, 0.f, 0.f);
            if (gr < M)
                v = *reinterpret_cast<const float4*>(A + (size_t)gr * K + gk);
            As[a_kc + 0][a_row] = v.x;
            As[a_kc + 1][a_row] = v.y;
            As[a_kc + 2][a_row] = v.z;
            As[a_kc + 3][a_row] = v.w;
        }
        // ---- load B tile ----
        {
            int gk = k0 + b_kk;
            int gn = bn + b_col;
            float4 v = make_float4(0.f, 0.f, 0.f, 0.f);
            const float* bp = B + (size_t)gk * N + gn;
            if (gn + 3 < N) {
                v = *reinterpret_cast<const float4*>(bp);
            } else if (gn < N) {
                v.x = bp[0];
                if (gn + 1 < N) v.y = bp[1];
                if (gn + 2 < N) v.z = bp[2];
            }
            *reinterpret_cast<float4*>(&Bs[b_kk][b_col]) = v;
        }
        __syncthreads();

#pragma unroll
        for (int kk = 0; kk < 8; kk++) {
            float a[8], b[8];
            *reinterpret_cast<float4*>(a)     = *reinterpret_cast<const float4*>(&As[kk][ty * 8]);
            *reinterpret_cast<float4*>(a + 4) = *reinterpret_cast<const float4*>(&As[kk][ty * 8 + 4]);
            *reinterpret_cast<float4*>(b)     = *reinterpret_cast<const float4*>(&Bs[kk][tx * 8]);
            *reinterpret_cast<float4*>(b + 4) = *reinterpret_cast<const float4*>(&Bs[kk][tx * 8 + 4]);
#pragma unroll
            for (int i = 0; i < 8; i++)
#pragma unroll
                for (int j = 0; j < 8; j++)
                    acc[i][j] += a[i] * b[j];
        }
        __syncthreads();
    }

    // ---- epilogue: + bias, store ----
#pragma unroll
    for (int i = 0; i < 8; i++) {
        int gr = bm + ty * 8 + i;
        if (gr >= M) continue;
        float* cp = C + (size_t)gr * N;
#pragma unroll
        for (int j = 0; j < 8; j++) {
            int gn = bn + tx * 8 + j;
            if (gn < N) cp[gn] = acc[i][j] + bias[gn];
        }
    }
}

// ---------------------------------------------------------------------------
// Gate: gate[row][s] = sigmoid( sum_k combined[row][k] * Wg[k][s] + bg[s] )
// One warp per row.
// ---------------------------------------------------------------------------
__global__ void gate_kernel(const float* __restrict__ Wg, const float* __restrict__ bg)
{
    int warp = (blockIdx.x * blockDim.x + threadIdx.x) >> 5;
    int lane = threadIdx.x & 31;
    if (warp >= MROWS) return;
    const float* row = g_comb + (size_t)warp * DS_;
    float acc[S_];
#pragma unroll
    for (int s = 0; s < S_; s++) acc[s] = 0.f;
    for (int k = lane; k < DS_; k += 32) {
        float c = row[k];
        const float* w = Wg + (size_t)k * S_;
#pragma unroll
        for (int s = 0; s < S_; s++) acc[s] += c * w[s];
    }
#pragma unroll
    for (int s = 0; s < S_; s++)
#pragma unroll
        for (int o = 16; o > 0; o >>= 1)
            acc[s] += __shfl_down_sync(0xffffffffu, acc[s], o);
    if (lane == 0) {
#pragma unroll
        for (int s = 0; s < S_; s++) {
            float v = acc[s] + bg[s];
            g_gate[(size_t)warp * S_ + s] = 1.f / (1.f + __expf(-v));
        }
    }
}

// ---------------------------------------------------------------------------
// Parallel linear-recurrence scan: y_l = g_l * y_{l-1} + (1-g_l) * sin_l, y_{-1}=0
// Composition (a,b): y_out = a*y_in + b;  seg compose: (a2,b2)∘(a1,b1)=(a2a1, a2b1+b2)
// 16 warps = one per (batch b, state s). Each lane owns 64 consecutive l.
// Overwrites g_comb cols 256..263 with the scanned states; writes final state out.
// ---------------------------------------------------------------------------
__global__ void scan_kernel(float* __restrict__ out_states /* 16 floats: [b][s] */)
{
    int warp = threadIdx.x >> 5;   // 0..15
    int lane = threadIdx.x & 31;
    int b = warp >> 3;
    int s = warp & 7;
    const int CH = L_ / 32;        // 64
    size_t rbase = (size_t)b * L_;
    int l0 = lane * CH;

    // Pass 1: local segment composition
    float A = 1.f, Bv = 0.f;
    for (int i = 0; i < CH; i++) {
        size_t r = rbase + l0 + i;
        float g  = g_gate[r * S_ + s];
        float si = g_comb[r * DS_ + D_ + s];
        Bv = g * Bv + (1.f - g) * si;
        A *= g;
    }
    // Inclusive warp scan of compositions
#pragma unroll
    for (int o = 1; o < 32; o <<= 1) {
        float Ap = __shfl_up_sync(0xffffffffu, A, o);
        float Bp = __shfl_up_sync(0xffffffffu, Bv, o);
        if (lane >= o) {
            Bv = A * Bp + Bv;   // apply earlier segment first
            A  = A * Ap;
        }
    }
    // Exclusive prefix -> state at my segment start (global y0 = 0)
    float y = __shfl_up_sync(0xffffffffu, Bv, 1);
    if (lane == 0) y = 0.f;

    // Pass 2: replay, writing states into combined[:, 256+s]
    for (int i = 0; i < CH; i++) {
        size_t r = rbase + l0 + i;
        float g  = g_gate[r * S_ + s];
        size_t idx = r * DS_ + D_ + s;
        float si = g_comb[idx];
        y = g * y + (1.f - g) * si;
        g_comb[idx] = y;
    }
    if (lane == 31) out_states[b * S_ + s] = y;
}

// ---------------------------------------------------------------------------
// LayerNorm: one warp per row of 256.
// ---------------------------------------------------------------------------
__global__ void ln_kernel(const float* __restrict__ gamma, const float* __restrict__ beta)
{
    int warp = (blockIdx.x * blockDim.x + threadIdx.x) >> 5;
    int lane = threadIdx.x & 31;
    if (warp >= MROWS) return;
    const float* x = g_h + (size_t)warp * D_;
    float v[8];
    *reinterpret_cast<float4*>(v)     = *reinterpret_cast<const float4*>(x + lane * 8);
    *reinterpret_cast<float4*>(v + 4) = *reinterpret_cast<const float4*>(x + lane * 8 + 4);
    float sum = 0.f;
#pragma unroll
    for (int i = 0; i < 8; i++) sum += v[i];
#pragma unroll
    for (int o = 16; o > 0; o >>= 1) sum += __shfl_xor_sync(0xffffffffu, sum, o);
    float mu = sum * (1.f / 256.f);
    float sq = 0.f;
#pragma unroll
    for (int i = 0; i < 8; i++) { float d = v[i] - mu; sq += d * d; }
#pragma unroll
    for (int o = 16; o > 0; o >>= 1) sq += __shfl_xor_sync(0xffffffffu, sq, o);
    float rstd = rsqrtf(sq * (1.f / 256.f) + 1e-5f);
    float* outp = g_hn + (size_t)warp * D_;
#pragma unroll
    for (int i = 0; i < 8; i++) {
        int c = lane * 8 + i;
        outp[c] = (v[i] - mu) * rstd * gamma[c] + beta[c];
    }
}

// ---------------------------------------------------------------------------
// Launch
// ---------------------------------------------------------------------------
extern "C" void kernel_launch(void* const* d_in, const int* in_sizes, int n_in,
                              void* d_out, int out_size)
{
    const int*   x_t   = (const int*)  d_in[0];
    const float* etab  = (const float*)d_in[1];
    const float* Wi    = (const float*)d_in[2];
    const float* bi    = (const float*)d_in[3];
    const float* Wg    = (const float*)d_in[4];
    const float* bg    = (const float*)d_in[5];
    const float* Wo    = (const float*)d_in[6];
    const float* bo    = (const float*)d_in[7];
    const float* gamma = (const float*)d_in[8];
    const float* beta  = (const float*)d_in[9];
    const float* Wc    = (const float*)d_in[10];
    const float* bc    = (const float*)d_in[11];
    const float* Wr    = (const float*)d_in[12];
    const float* br    = (const float*)d_in[13];
    float* out = (float*)d_out;

    // Output layout: logits (2*2048*32000) | recon (2*2048*256) | states (4*2*8)
    float* out_logits = out;
    float* out_recon  = out + (size_t)MROWS * VOCAB_;
    float* out_states = out + (size_t)MROWS * VOCAB_ + (size_t)MROWS * D_;

    float *p_h, *p_comb, *p_hn;
    cudaGetSymbolAddress((void**)&p_h,    g_h);
    cudaGetSymbolAddress((void**)&p_comb, g_comb);
    cudaGetSymbolAddress((void**)&p_hn,   g_hn);

    // 1. Embedding gather
    embed_kernel<<<MROWS, 64>>>(x_t, etab);

    // 2. Four thunder-core layers
    for (int i = 0; i < DEPTH_; i++) {
        const float* Wi_i = Wi + (size_t)i * D_ * DS_;
        const float* bi_i = bi + (size_t)i * DS_;
        const float* Wg_i = Wg + (size_t)i * DS_ * S_;
        const float* bg_i = bg + (size_t)i * S_;
        const float* Wo_i = Wo + (size_t)i * DS_ * D_;
        const float* bo_i = bo + (size_t)i * D_;

        // combined = h @ Wi + bi   (4096 x 264, K=256)
        {
            dim3 grid((DS_ + 127) / 128, MROWS / 128);
            sgemm_bias<<<grid, 256>>>(p_h, Wi_i, bi_i, p_comb, MROWS, DS_, D_);
        }
        // gate = sigmoid(combined @ Wg + bg)
        gate_kernel<<<MROWS / 8, 256>>>(Wg_i, bg_i);
        // recurrence scan (overwrites combined cols 256..263 with states)
        scan_kernel<<<1, 512>>>(out_states + (size_t)i * B_ * S_);
        // h = [embed_part | states] @ Wo + bo   (4096 x 256, K=264)
        {
            dim3 grid(D_ / 128, MROWS / 128);
            sgemm_bias<<<grid, 256>>>(p_comb, Wo_i, bo_i, p_h, MROWS, D_, DS_);
        }
    }

    // 3. LayerNorm
    ln_kernel<<<MROWS / 8, 256>>>(gamma, beta);

    // 4. logits = hn @ Wc + bc   (4096 x 32000, K=256)  -- dominant GEMM
    {
        dim3 grid(VOCAB_ / 128, MROWS / 128);
        sgemm_bias<<<grid, 256>>>(p_hn, Wc, bc, out_logits, MROWS, VOCAB_, D_);
    }

    // 5. recon = hn @ Wr + br   (4096 x 256, K=256)
    {
        dim3 grid(D_ / 128, MROWS / 128);
        sgemm_bias<<<grid, 256>>>(p_hn, Wr, br, out_recon, MROWS, D_, D_);
    }
}

// round 3
// speedup vs baseline: 1.8176x; 1.8176x over previous
#include <cuda_runtime.h>
#include <cuda_bf16.h>
#include <cstdint>

#define D_     256
#define S_     8
#define DS_    264
#define DEPTH_ 4
#define VOCAB_ 32000
#define MROWS  4096
#define L_     2048
#define B_     2

// ---------------- scratch (device globals; no allocation allowed) ----------
__device__ float g_h[MROWS * D_];
__device__ float g_comb[MROWS * DS_];
__device__ float g_hn[MROWS * D_];
__device__ float g_ga[S_ * MROWS];           // gates, column-major [s][row]
__device__ float g_gb[S_ * MROWS];           // (1-g)*state_in, column-major
__device__ __nv_bfloat16 g_ahi[MROWS * D_];  // hn split hi
__device__ __nv_bfloat16 g_alo[MROWS * D_];  // hn split lo
__device__ __nv_bfloat16 g_bhi[VOCAB_ * D_]; // WcT split hi  [v][d]
__device__ __nv_bfloat16 g_blo[VOCAB_ * D_]; // WcT split lo

// ---------------- PTX helpers (baseline features only: sm_80-era) ----------
__device__ __forceinline__ uint32_t smem_u32(const void* p) {
    uint32_t a;
    asm("{ .reg .u64 t; cvta.to.shared.u64 t, %1; cvt.u32.u64 %0, t; }" : "=r"(a) : "l"(p));
    return a;
}
#define CP_ASYNC16(dst, src) \
    asm volatile("cp.async.cg.shared.global [%0], [%1], 16;" :: "r"(dst), "l"(src))
#define CP_COMMIT() asm volatile("cp.async.commit_group;" ::: "memory")
#define CP_WAIT1()  asm volatile("cp.async.wait_group 1;" ::: "memory")
#define LDSM4(r0, r1, r2, r3, addr) \
    asm volatile("ldmatrix.sync.aligned.m8n8.x4.shared.b16 {%0,%1,%2,%3}, [%4];" \
                 : "=r"(r0), "=r"(r1), "=r"(r2), "=r"(r3) : "r"(addr))
#define MMA16816(d, a, b) \
    asm volatile("mma.sync.aligned.m16n8k16.row.col.f32.bf16.bf16.f32 " \
                 "{%0,%1,%2,%3}, {%4,%5,%6,%7}, {%8,%9}, {%0,%1,%2,%3};" \
                 : "+f"((d)[0]), "+f"((d)[1]), "+f"((d)[2]), "+f"((d)[3]) \
                 : "r"((a)[0]), "r"((a)[1]), "r"((a)[2]), "r"((a)[3]), \
                   "r"((b)[0]), "r"((b)[1]))

// ---------------- embed ------------------------------------------------------
__global__ void embed_kernel(const int* __restrict__ x, const float* __restrict__ tab)
{
    int row = blockIdx.x;
    int t   = threadIdx.x;
    int tok = x[row];
    const float4* src = reinterpret_cast<const float4*>(tab + (size_t)tok * D_);
    float4* dst = reinterpret_cast<float4*>(g_h + (size_t)row * D_);
    dst[t] = src[t];
}

// ---------------- FFMA SGEMM (small GEMMs) ----------------------------------
__global__ void __launch_bounds__(256)
sgemm_bias(const float* __restrict__ A, const float* __restrict__ B,
           const float* __restrict__ bias, float* __restrict__ C,
           int M, int N, int K)
{
    __shared__ float As[8][128];
    __shared__ float Bs[8][128];
    int tid = threadIdx.x;
    int tx = tid & 15, ty = tid >> 4;
    int bm = blockIdx.y * 128, bn = blockIdx.x * 128;
    float acc[8][8];
#pragma unroll
    for (int i = 0; i < 8; i++)
#pragma unroll
        for (int j = 0; j < 8; j++) acc[i][j] = 0.f;
    int a_row = tid >> 1, a_kc = (tid & 1) * 4;
    int b_kk = tid >> 5, b_col = (tid & 31) * 4;
    for (int k0 = 0; k0 < K; k0 += 8) {
        {
            int gr = bm + a_row, gk = k0 + a_kc;
            float4 v = make_float4(0.f, 0.f, 0.f, 0.f);
            if (gr < M) v = *reinterpret_cast<const float4*>(A + (size_t)gr * K + gk);
            As[a_kc + 0][a_row] = v.x; As[a_kc + 1][a_row] = v.y;
            As[a_kc + 2][a_row] = v.z; As[a_kc + 3][a_row] = v.w;
        }
        {
            int gk = k0 + b_kk, gn = bn + b_col;
            float4 v = make_float4(0.f, 0.f, 0.f, 0.f);
            const float* bp = B + (size_t)gk * N + gn;
            if (gn + 3 < N) v = *reinterpret_cast<const float4*>(bp);
            else if (gn < N) {
                v.x = bp[0];
                if (gn + 1 < N) v.y = bp[1];
                if (gn + 2 < N) v.z = bp[2];
            }
            *reinterpret_cast<float4*>(&Bs[b_kk][b_col]) = v;
        }
        __syncthreads();
#pragma unroll
        for (int kk = 0; kk < 8; kk++) {
            float a[8], b[8];
            *reinterpret_cast<float4*>(a)     = *reinterpret_cast<const float4*>(&As[kk][ty * 8]);
            *reinterpret_cast<float4*>(a + 4) = *reinterpret_cast<const float4*>(&As[kk][ty * 8 + 4]);
            *reinterpret_cast<float4*>(b)     = *reinterpret_cast<const float4*>(&Bs[kk][tx * 8]);
            *reinterpret_cast<float4*>(b + 4) = *reinterpret_cast<const float4*>(&Bs[kk][tx * 8 + 4]);
#pragma unroll
            for (int i = 0; i < 8; i++)
#pragma unroll
                for (int j = 0; j < 8; j++) acc[i][j] += a[i] * b[j];
        }
        __syncthreads();
    }
#pragma unroll
    for (int i = 0; i < 8; i++) {
        int gr = bm + ty * 8 + i;
        if (gr >= M) continue;
        float* cp = C + (size_t)gr * N;
#pragma unroll
        for (int j = 0; j < 8; j++) {
            int gn = bn + tx * 8 + j;
            if (gn < N) cp[gn] = acc[i][j] + bias[gn];
        }
    }
}

// ---------------- gate: sigmoid + compact scan inputs ------------------------
__global__ void gate_kernel(const float* __restrict__ Wg, const float* __restrict__ bg)
{
    int warp = (blockIdx.x * blockDim.x + threadIdx.x) >> 5;
    int lane = threadIdx.x & 31;
    if (warp >= MROWS) return;
    const float* row = g_comb + (size_t)warp * DS_;
    float acc[S_];
#pragma unroll
    for (int s = 0; s < S_; s++) acc[s] = 0.f;
    for (int k = lane; k < DS_; k += 32) {
        float c = row[k];
        const float* w = Wg + (size_t)k * S_;
#pragma unroll
        for (int s = 0; s < S_; s++) acc[s] += c * w[s];
    }
#pragma unroll
    for (int s = 0; s < S_; s++)
#pragma unroll
        for (int o = 16; o > 0; o >>= 1)
            acc[s] += __shfl_down_sync(0xffffffffu, acc[s], o);
    if (lane == 0) {
#pragma unroll
        for (int s = 0; s < S_; s++) {
            float g = 1.f / (1.f + __expf(-(acc[s] + bg[s])));
            float sin_v = row[D_ + s];
            g_ga[(size_t)s * MROWS + warp] = g;
            g_gb[(size_t)s * MROWS + warp] = (1.f - g) * sin_v;
        }
    }
}

// ---------------- scan: 1024 threads, 2 warps per (b,s) ----------------------
__global__ void __launch_bounds__(1024)
scan_kernel(float* __restrict__ out_states)
{
    __shared__ float warp_tot[16];
    int w = threadIdx.x >> 5;
    int lane = threadIdx.x & 31;
    int pair = w >> 1;          // 0..15
    int half = w & 1;
    int b = pair >> 3, s = pair & 7;
    const float* ga = g_ga + (size_t)s * MROWS + (size_t)b * L_ + half * 1024;
    const float* gb = g_gb + (size_t)s * MROWS + (size_t)b * L_ + half * 1024;
    int l0 = lane * 32;

    float A = 1.f, Bv = 0.f;
#pragma unroll
    for (int i4 = 0; i4 < 8; i4++) {
        float4 gv = *reinterpret_cast<const float4*>(ga + l0 + i4 * 4);
        float4 bv = *reinterpret_cast<const float4*>(gb + l0 + i4 * 4);
        Bv = gv.x * Bv + bv.x; A *= gv.x;
        Bv = gv.y * Bv + bv.y; A *= gv.y;
        Bv = gv.z * Bv + bv.z; A *= gv.z;
        Bv = gv.w * Bv + bv.w; A *= gv.w;
    }
#pragma unroll
    for (int o = 1; o < 32; o <<= 1) {
        float Ap = __shfl_up_sync(0xffffffffu, A, o);
        float Bp = __shfl_up_sync(0xffffffffu, Bv, o);
        if (lane >= o) { Bv = A * Bp + Bv; A = A * Ap; }
    }
    if (half == 0 && lane == 31) warp_tot[pair] = Bv;
    __syncthreads();
    float y_w = (half == 0) ? 0.f : warp_tot[pair];
    float Aex = __shfl_up_sync(0xffffffffu, A, 1);
    float Bex = __shfl_up_sync(0xffffffffu, Bv, 1);
    if (lane == 0) { Aex = 1.f; Bex = 0.f; }
    float y = Aex * y_w + Bex;

    size_t rbase = (size_t)b * L_ + half * 1024 + l0;
#pragma unroll
    for (int i4 = 0; i4 < 8; i4++) {
        float4 gv = *reinterpret_cast<const float4*>(ga + l0 + i4 * 4);
        float4 bv = *reinterpret_cast<const float4*>(gb + l0 + i4 * 4);
        y = gv.x * y + bv.x; g_comb[(rbase + i4 * 4 + 0) * DS_ + D_ + s] = y;
        y = gv.y * y + bv.y; g_comb[(rbase + i4 * 4 + 1) * DS_ + D_ + s] = y;
        y = gv.z * y + bv.z; g_comb[(rbase + i4 * 4 + 2) * DS_ + D_ + s] = y;
        y = gv.w * y + bv.w; g_comb[(rbase + i4 * 4 + 3) * DS_ + D_ + s] = y;
    }
    if (half == 1 && lane == 31) out_states[b * S_ + s] = y;
}

// ---------------- layernorm + bf16 hi/lo split -------------------------------
__global__ void ln_kernel(const float* __restrict__ gamma, const float* __restrict__ beta)
{
    int warp = (blockIdx.x * blockDim.x + threadIdx.x) >> 5;
    int lane = threadIdx.x & 31;
    if (warp >= MROWS) return;
    const float* x = g_h + (size_t)warp * D_;
    float v[8];
    *reinterpret_cast<float4*>(v)     = *reinterpret_cast<const float4*>(x + lane * 8);
    *reinterpret_cast<float4*>(v + 4) = *reinterpret_cast<const float4*>(x + lane * 8 + 4);
    float sum = 0.f;
#pragma unroll
    for (int i = 0; i < 8; i++) sum += v[i];
#pragma unroll
    for (int o = 16; o > 0; o >>= 1) sum += __shfl_xor_sync(0xffffffffu, sum, o);
    float mu = sum * (1.f / 256.f);
    float sq = 0.f;
#pragma unroll
    for (int i = 0; i < 8; i++) { float d = v[i] - mu; sq += d * d; }
#pragma unroll
    for (int o = 16; o > 0; o >>= 1) sq += __shfl_xor_sync(0xffffffffu, sq, o);
    float rstd = rsqrtf(sq * (1.f / 256.f) + 1e-5f);
    float* outp = g_hn + (size_t)warp * D_;
    __nv_bfloat16* hip = g_ahi + (size_t)warp * D_;
    __nv_bfloat16* lop = g_alo + (size_t)warp * D_;
#pragma unroll
    for (int i = 0; i < 8; i++) {
        int c = lane * 8 + i;
        float y = (v[i] - mu) * rstd * gamma[c] + beta[c];
        outp[c] = y;
        __nv_bfloat16 hi = __float2bfloat16(y);
        hip[c] = hi;
        lop[c] = __float2bfloat16(y - __bfloat162float(hi));
    }
}

// ---------------- Wc transpose + bf16 hi/lo split ----------------------------
__global__ void __launch_bounds__(256)
split_wc(const float* __restrict__ Wc)   // [D_][VOCAB_]
{
    __shared__ float tile[32][33];
    int tx = threadIdx.x & 31, ty = threadIdx.x >> 5;
    int v0 = blockIdx.x * 32, d0 = blockIdx.y * 32;
#pragma unroll
    for (int i = 0; i < 4; i++) {
        int d = d0 + ty + i * 8;
        tile[ty + i * 8][tx] = Wc[(size_t)d * VOCAB_ + v0 + tx];
    }
    __syncthreads();
#pragma unroll
    for (int i = 0; i < 4; i++) {
        int v = v0 + ty + i * 8;
        float x = tile[tx][ty + i * 8];
        __nv_bfloat16 hi = __float2bfloat16(x);
        g_bhi[(size_t)v * D_ + d0 + tx] = hi;
        g_blo[(size_t)v * D_ + d0 + tx] = __float2bfloat16(x - __bfloat162float(hi));
    }
}

// ---------------- logits: mma.sync bf16 3-split GEMM -------------------------
// C[4096,32000] = hn @ WcT^T + bc via AhiBhi + AloBhi + AhiBlo (fp32 accum).
// CTA tile 128x128, 8 warps (64x32 each), K-chunk 32 bf16, 3-stage cp.async.
// smem row = 64B (32 bf16); swizzle: 16B-chunk c' = c ^ ((row>>1)&3).
#define STAGE_BYTES 16384     // 8KB A + 8KB B
__global__ void __launch_bounds__(256)
logits_mma(const float* __restrict__ bc, float* __restrict__ out)
{
    __shared__ char smem[3 * STAGE_BYTES];
    uint32_t sb = smem_u32(smem);
    int tid = threadIdx.x;
    int lane = tid & 31;
    int warp = tid >> 5;
    int wm = warp >> 2;          // 0..1 -> m offset *64
    int wn = warp & 3;           // 0..3 -> n offset *32
    int m0 = blockIdx.y * 128;
    int n0 = blockIdx.x * 128;

    // staging thread mapping (2 x 16B per tile per thread)
    int st_r0 = tid >> 2;                 // rows 0..63   (i=0)
    int st_r1 = (tid + 256) >> 2;         // rows 64..127 (i=1)
    int st_c  = tid & 3;
    uint32_t st_off0 = (uint32_t)(st_r0 * 64 + ((st_c ^ ((st_r0 >> 1) & 3)) << 4));
    uint32_t st_off1 = (uint32_t)(st_r1 * 64 + ((st_c ^ ((st_r1 >> 1) & 3)) << 4));

    const __nv_bfloat16* APl[3] = { g_ahi, g_alo, g_ahi };
    const __nv_bfloat16* BPl[3] = { g_bhi, g_bhi, g_blo };

    // ldmatrix per-lane base offsets
    int arow[4], brow[2];
    uint32_t aswz[4], bswz[2];
#pragma unroll
    for (int mt = 0; mt < 4; mt++) {
        int r = wm * 64 + mt * 16 + (lane & 15);
        arow[mt] = r * 64;
        aswz[mt] = (r >> 1) & 3;
    }
#pragma unroll
    for (int g = 0; g < 2; g++) {
        int r = wn * 32 + g * 16 + (lane & 15);
        brow[g] = r * 64;
        bswz[g] = (r >> 1) & 3;
    }
    uint32_t chi = (uint32_t)(lane >> 4);   // 16B chunk half select

    float acc[4][4][4];
#pragma unroll
    for (int i = 0; i < 4; i++)
#pragma unroll
        for (int j = 0; j < 4; j++)
#pragma unroll
            for (int r = 0; r < 4; r++) acc[i][j][r] = 0.f;

    // ---- pipeline ----
    // chunk ci in [0,24): pass = ci>>3, kc = (ci&7)*32
#define ISSUE(ci, stg)                                                          \
    do {                                                                        \
        int _p = (ci) >> 3;                                                     \
        int _kc = ((ci) & 7) * 32;                                              \
        const __nv_bfloat16* _A = APl[_p];                                      \
        const __nv_bfloat16* _B = BPl[_p];                                      \
        uint32_t _sa = sb + (stg) * STAGE_BYTES;                                \
        uint32_t _sbm = _sa + 8192;                                             \
        CP_ASYNC16(_sa + st_off0, _A + (size_t)(m0 + st_r0) * 256 + _kc + st_c * 8); \
        CP_ASYNC16(_sa + st_off1, _A + (size_t)(m0 + st_r1) * 256 + _kc + st_c * 8); \
        CP_ASYNC16(_sbm + st_off0, _B + (size_t)(n0 + st_r0) * 256 + _kc + st_c * 8); \
        CP_ASYNC16(_sbm + st_off1, _B + (size_t)(n0 + st_r1) * 256 + _kc + st_c * 8); \
    } while (0)

    ISSUE(0, 0); CP_COMMIT();
    ISSUE(1, 1); CP_COMMIT();

    for (int ci = 0; ci < 24; ci++) {
        CP_WAIT1();
        __syncthreads();
        if (ci + 2 < 24) ISSUE(ci + 2, (ci + 2) % 3);
        CP_COMMIT();

        uint32_t sa = sb + (ci % 3) * STAGE_BYTES;
        uint32_t sbm = sa + 8192;
#pragma unroll
        for (int ks = 0; ks < 2; ks++) {
            uint32_t c = 2 * ks + chi;
            uint32_t af[4][4], bf[4][2];
#pragma unroll
            for (int mt = 0; mt < 4; mt++) {
                uint32_t addr = sa + arow[mt] + (((c ^ aswz[mt])) << 4);
                LDSM4(af[mt][0], af[mt][1], af[mt][2], af[mt][3], addr);
            }
#pragma unroll
            for (int g = 0; g < 2; g++) {
                uint32_t addr = sbm + brow[g] + (((c ^ bswz[g])) << 4);
                uint32_t t0, t1, t2, t3;
                LDSM4(t0, t1, t2, t3, addr);
                bf[2 * g + 0][0] = t0; bf[2 * g + 1][0] = t1;
                bf[2 * g + 0][1] = t2; bf[2 * g + 1][1] = t3;
            }
#pragma unroll
            for (int mt = 0; mt < 4; mt++)
#pragma unroll
                for (int nt = 0; nt < 4; nt++)
                    MMA16816(acc[mt][nt], af[mt], bf[nt]);
        }
    }
#undef ISSUE

    // ---- epilogue: +bias, float2 stores ----
#pragma unroll
    for (int mt = 0; mt < 4; mt++) {
        int row0 = m0 + wm * 64 + mt * 16 + (lane >> 2);
#pragma unroll
        for (int nt = 0; nt < 4; nt++) {
            int col = n0 + wn * 32 + nt * 8 + (lane & 3) * 2;
            float2 b2 = *reinterpret_cast<const float2*>(bc + col);
            float2 o0, o1;
            o0.x = acc[mt][nt][0] + b2.x;  o0.y = acc[mt][nt][1] + b2.y;
            o1.x = acc[mt][nt][2] + b2.x;  o1.y = acc[mt][nt][3] + b2.y;
            *reinterpret_cast<float2*>(out + (size_t)row0 * VOCAB_ + col) = o0;
            *reinterpret_cast<float2*>(out + (size_t)(row0 + 8) * VOCAB_ + col) = o1;
        }
    }
}

// ---------------- launch -----------------------------------------------------
extern "C" void kernel_launch(void* const* d_in, const int* in_sizes, int n_in,
                              void* d_out, int out_size)
{
    const int*   x_t   = (const int*)  d_in[0];
    const float* etab  = (const float*)d_in[1];
    const float* Wi    = (const float*)d_in[2];
    const float* bi    = (const float*)d_in[3];
    const float* Wg    = (const float*)d_in[4];
    const float* bg    = (const float*)d_in[5];
    const float* Wo    = (const float*)d_in[6];
    const float* bo    = (const float*)d_in[7];
    const float* gamma = (const float*)d_in[8];
    const float* beta  = (const float*)d_in[9];
    const float* Wc    = (const float*)d_in[10];
    const float* bc    = (const float*)d_in[11];
    const float* Wr    = (const float*)d_in[12];
    const float* br    = (const float*)d_in[13];
    float* out = (float*)d_out;

    float* out_logits = out;
    float* out_recon  = out + (size_t)MROWS * VOCAB_;
    float* out_states = out_recon + (size_t)MROWS * D_;

    float *p_h, *p_comb, *p_hn;
    cudaGetSymbolAddress((void**)&p_h,    g_h);
    cudaGetSymbolAddress((void**)&p_comb, g_comb);
    cudaGetSymbolAddress((void**)&p_hn,   g_hn);

    // weight split/transpose (independent of activations; runs up front)
    split_wc<<<dim3(VOCAB_ / 32, D_ / 32), 256>>>(Wc);

    embed_kernel<<<MROWS, 64>>>(x_t, etab);

    for (int i = 0; i < DEPTH_; i++) {
        const float* Wi_i = Wi + (size_t)i * D_ * DS_;
        const float* bi_i = bi + (size_t)i * DS_;
        const float* Wg_i = Wg + (size_t)i * DS_ * S_;
        const float* bg_i = bg + (size_t)i * S_;
        const float* Wo_i = Wo + (size_t)i * DS_ * D_;
        const float* bo_i = bo + (size_t)i * D_;

        {
            dim3 grid((DS_ + 127) / 128, MROWS / 128);
            sgemm_bias<<<grid, 256>>>(p_h, Wi_i, bi_i, p_comb, MROWS, DS_, D_);
        }
        gate_kernel<<<MROWS / 8, 256>>>(Wg_i, bg_i);
        scan_kernel<<<1, 1024>>>(out_states + (size_t)i * B_ * S_);
        {
            dim3 grid(D_ / 128, MROWS / 128);
            sgemm_bias<<<grid, 256>>>(p_comb, Wo_i, bo_i, p_h, MROWS, D_, DS_);
        }
    }

    ln_kernel<<<MROWS / 8, 256>>>(gamma, beta);

    // logits via mma.sync tensor cores
    logits_mma<<<dim3(VOCAB_ / 128, MROWS / 128), 256>>>(bc, out_logits);

    // recon (small, FFMA)
    {
        dim3 grid(D_ / 128, MROWS / 128);
        sgemm_bias<<<grid, 256>>>(p_hn, Wr, br, out_recon, MROWS, D_, D_);
    }
}